// round 1
// baseline (speedup 1.0000x reference)
#include <cuda_runtime.h>

#define Bn 8192
#define Dn 256
#define INn 64
#define ONn 256

// scratch: inner activations, stored transposed [d][b] for coalescing both ways
__device__ float g_innerT[(size_t)Dn * Bn];

// ---------------------------------------------------------------------------
// K1: inner[b,d] = sum_i relu(x[b,d]*w1[d,i]+b1[d,i])*w2[d,i] + b2[d]
// grid (B/128, D/64), 256 threads. smem: w1/b1/w2 chunk (48KB) + xT tile (33KB)
// ---------------------------------------------------------------------------
__global__ __launch_bounds__(256, 2) void kan_inner(
    const float* __restrict__ x, const float* __restrict__ w1,
    const float* __restrict__ b1, const float* __restrict__ w2,
    const float* __restrict__ b2)
{
    extern __shared__ float sm[];
    float* sw1 = sm;                 // [64][64]
    float* sb1 = sm + 4096;          // [64][64]
    float* sw2 = sm + 8192;          // [64][64]
    float* sx  = sm + 12288;         // [64 d][129 b] padded, transposed x tile

    const int b0 = blockIdx.x << 7;  // *128
    const int d0 = blockIdx.y << 6;  // *64
    const int t  = threadIdx.x;

    // load weight chunk (rows d0..d0+63), coalesced float4
    {
        const float4* gw1 = (const float4*)(w1 + (size_t)d0 * INn);
        const float4* gb1 = (const float4*)(b1 + (size_t)d0 * INn);
        const float4* gw2 = (const float4*)(w2 + (size_t)d0 * INn);
        #pragma unroll
        for (int k = t; k < 1024; k += 256) {
            ((float4*)sw1)[k] = gw1[k];
            ((float4*)sb1)[k] = gb1[k];
            ((float4*)sw2)[k] = gw2[k];
        }
    }
    // load x tile [128 b][64 d] coalesced, store transposed sx[d][b]
    #pragma unroll
    for (int k = t; k < 2048; k += 256) {
        int b = k >> 4;
        int c = (k & 15) << 2;
        float4 v = *(const float4*)(x + (size_t)(b0 + b) * Dn + d0 + c);
        sx[(c + 0) * 129 + b] = v.x;
        sx[(c + 1) * 129 + b] = v.y;
        sx[(c + 2) * 129 + b] = v.z;
        sx[(c + 3) * 129 + b] = v.w;
    }
    __syncthreads();

    const int warp = t >> 5, lane = t & 31;
    #pragma unroll 1
    for (int j = 0; j < 8; ++j) {
        const int dl = warp + (j << 3);       // d_local, fixed per warp => weight broadcast
        const float xv0 = sx[dl * 129 + lane];
        const float xv1 = sx[dl * 129 + lane + 32];
        const float xv2 = sx[dl * 129 + lane + 64];
        const float xv3 = sx[dl * 129 + lane + 96];
        float a0 = 0.f, a1 = 0.f, a2 = 0.f, a3 = 0.f;
        const float* pw1 = sw1 + (dl << 6);
        const float* pb1 = sb1 + (dl << 6);
        const float* pw2 = sw2 + (dl << 6);
        #pragma unroll
        for (int i = 0; i < INn; i += 4) {
            float wa[4], ba[4], va[4];
            *(float4*)wa = *(const float4*)(pw1 + i);
            *(float4*)ba = *(const float4*)(pb1 + i);
            *(float4*)va = *(const float4*)(pw2 + i);
            #pragma unroll
            for (int c = 0; c < 4; ++c) {
                float h;
                h = fmaxf(fmaf(xv0, wa[c], ba[c]), 0.f); a0 = fmaf(h, va[c], a0);
                h = fmaxf(fmaf(xv1, wa[c], ba[c]), 0.f); a1 = fmaf(h, va[c], a1);
                h = fmaxf(fmaf(xv2, wa[c], ba[c]), 0.f); a2 = fmaf(h, va[c], a2);
                h = fmaxf(fmaf(xv3, wa[c], ba[c]), 0.f); a3 = fmaf(h, va[c], a3);
            }
        }
        const float bias = __ldg(b2 + d0 + dl);
        float* op = g_innerT + (size_t)(d0 + dl) * Bn + b0;
        op[lane]      = a0 + bias;     // coalesced: lanes = consecutive b
        op[lane + 32] = a1 + bias;
        op[lane + 64] = a2 + bias;
        op[lane + 96] = a3 + bias;
    }
}

// ---------------------------------------------------------------------------
// K2: g = relu(inner @ wo1^T + bo1); out = g @ wo2^T + bo2
// grid B/64 = 128 blocks, 256 threads. smem: inner tile + wo1 + wo2 + gT (208KB)
// ---------------------------------------------------------------------------
__global__ __launch_bounds__(256, 1) void kan_outer(
    const float* __restrict__ wo1, const float* __restrict__ bo1,
    const float* __restrict__ wo2, const float* __restrict__ bo2,
    float* __restrict__ out)
{
    extern __shared__ float sm[];
    float* sIn = sm;                  // [256 d][64 b]   (= innerT layout)
    float* sW1 = sm + 16384;          // [64 i][256 d]   (natural wo1 layout)
    float* sW2 = sW1 + 16384;         // [256 o][64 i]   (natural wo2 layout)
    float* sgT = sW2 + 16384;         // [64 i][64 b]
    float* sOut = sm;                 // [64 b][132] output staging, reuses sIn

    const int b0 = blockIdx.x << 6;   // *64
    const int t  = threadIdx.x;

    // loads: inner tile (coalesced from innerT), wo1, wo2 straight copies
    #pragma unroll
    for (int k = t; k < 4096; k += 256) {
        int d = k >> 4, c = (k & 15) << 2;
        *(float4*)(sIn + d * 64 + c) =
            *(const float4*)(g_innerT + (size_t)d * Bn + b0 + c);
        ((float4*)sW1)[k] = ((const float4*)wo1)[k];
        ((float4*)sW2)[k] = ((const float4*)wo2)[k];
    }
    __syncthreads();

    const int hi = t >> 4;   // 0..15 (quasi-uniform within warp: 2 values)
    const int lo = t & 15;   // 0..15 (varies across lanes)

    // ---- Phase A: g[b][i], thread tile 4b x 4i; i-group = hi, b-group = lo
    {
        float a[4][4];
        #pragma unroll
        for (int bb = 0; bb < 4; ++bb)
            #pragma unroll
            for (int ii = 0; ii < 4; ++ii) a[bb][ii] = 0.f;

        const float* pin = sIn + (lo << 2);
        const float* pw  = sW1 + (hi << 2) * 256;
        #pragma unroll 2
        for (int d = 0; d < 256; d += 4) {
            float xv[4][4];  // [dd][bb]
            float wv[4][4];  // [ii][dd]
            #pragma unroll
            for (int dd = 0; dd < 4; ++dd)
                *(float4*)xv[dd] = *(const float4*)(pin + (d + dd) * 64);
            #pragma unroll
            for (int ii = 0; ii < 4; ++ii)
                *(float4*)wv[ii] = *(const float4*)(pw + ii * 256 + d);
            #pragma unroll
            for (int dd = 0; dd < 4; ++dd)
                #pragma unroll
                for (int bb = 0; bb < 4; ++bb)
                    #pragma unroll
                    for (int ii = 0; ii < 4; ++ii)
                        a[bb][ii] = fmaf(xv[dd][bb], wv[ii][dd], a[bb][ii]);
        }
        float bo1a[4];
        *(float4*)bo1a = __ldg((const float4*)(bo1 + (hi << 2)));
        #pragma unroll
        for (int ii = 0; ii < 4; ++ii)
            #pragma unroll
            for (int bb = 0; bb < 4; ++bb)
                sgT[((hi << 2) + ii) * 64 + (lo << 2) + bb] =
                    fmaxf(a[bb][ii] + bo1a[ii], 0.f);
    }
    __syncthreads();

    // ---- Phase B: out[b][o], thread tile 4b x 8o, two o-passes
    // o-group = hi (quasi-uniform => wo2 reads broadcast), b-group = lo
    for (int pass = 0; pass < 2; ++pass) {
        const int obase = (pass << 7) + (hi << 3);
        float acc[4][8];
        #pragma unroll
        for (int bb = 0; bb < 4; ++bb)
            #pragma unroll
            for (int oo = 0; oo < 8; ++oo) acc[bb][oo] = 0.f;

        #pragma unroll 4
        for (int i = 0; i < 64; i += 4) {
            float gv[4][4];  // [ii][bb]
            float wv[8][4];  // [oo][ii]
            #pragma unroll
            for (int ii = 0; ii < 4; ++ii)
                *(float4*)gv[ii] = *(const float4*)(sgT + (i + ii) * 64 + (lo << 2));
            #pragma unroll
            for (int oo = 0; oo < 8; ++oo)
                *(float4*)wv[oo] = *(const float4*)(sW2 + (obase + oo) * 64 + i);
            #pragma unroll
            for (int ii = 0; ii < 4; ++ii)
                #pragma unroll
                for (int bb = 0; bb < 4; ++bb)
                    #pragma unroll
                    for (int oo = 0; oo < 8; ++oo)
                        acc[bb][oo] = fmaf(gv[ii][bb], wv[oo][ii], acc[bb][oo]);
        }

        float bo2a[4], bo2b[4];
        *(float4*)bo2a = __ldg((const float4*)(bo2 + obase));
        *(float4*)bo2b = __ldg((const float4*)(bo2 + obase + 4));

        // stage in smem, then coalesced store
        #pragma unroll
        for (int bb = 0; bb < 4; ++bb) {
            int b = (lo << 2) + bb;
            float r[8];
            #pragma unroll
            for (int oo = 0; oo < 4; ++oo) r[oo]     = acc[bb][oo]     + bo2a[oo];
            #pragma unroll
            for (int oo = 0; oo < 4; ++oo) r[oo + 4] = acc[bb][oo + 4] + bo2b[oo];
            *(float4*)(sOut + b * 132 + (hi << 3))     = *(float4*)r;
            *(float4*)(sOut + b * 132 + (hi << 3) + 4) = *(float4*)(r + 4);
        }
        __syncthreads();
        #pragma unroll
        for (int k = t; k < 2048; k += 256) {
            int b = k >> 5;
            int c = (k & 31) << 2;
            *(float4*)(out + (size_t)(b0 + b) * ONn + (pass << 7) + c) =
                *(const float4*)(sOut + b * 132 + c);
        }
        __syncthreads();
    }
}

// ---------------------------------------------------------------------------
extern "C" void kernel_launch(void* const* d_in, const int* in_sizes, int n_in,
                              void* d_out, int out_size)
{
    const float* x   = (const float*)d_in[0];
    const float* w1  = (const float*)d_in[1];
    const float* b1  = (const float*)d_in[2];
    const float* w2  = (const float*)d_in[3];
    const float* b2  = (const float*)d_in[4];
    const float* wo1 = (const float*)d_in[5];
    const float* bo1 = (const float*)d_in[6];
    const float* wo2 = (const float*)d_in[7];
    const float* bo2 = (const float*)d_in[8];
    float* out = (float*)d_out;

    const int smem1 = (12288 + 64 * 129) * 4;                    // 82176 B
    const int smem2 = (16384 * 3 + 4096) * 4;                    // 212992 B
    cudaFuncSetAttribute(kan_inner, cudaFuncAttributeMaxDynamicSharedMemorySize, smem1);
    cudaFuncSetAttribute(kan_outer, cudaFuncAttributeMaxDynamicSharedMemorySize, smem2);

    kan_inner<<<dim3(Bn / 128, Dn / 64), 256, smem1>>>(x, w1, b1, w2, b2);
    kan_outer<<<Bn / 64, 256, smem2>>>(wo1, bo1, wo2, bo2, out);
}